// round 12
// baseline (speedup 1.0000x reference)
#include <cuda_runtime.h>
#include <math.h>
#include <stdint.h>

// ---------------------------------------------------------------------------
// GRU: T=512, B=1024, H=128.  out = h_T @ w_out^T + b_out
//
// Crossbar-aware lane maps — every LDS request <= 128B after broadcast:
// Phase 1: warp = u-octet, lanes (rl,ul); thread: 8 strided rows, full k.
//          Weight LDS = 128B/instr (1 cyc), x LDS = 64B broadcast (1 cyc).
// Phase 2: 512 thr, split-K-4: thread (u, kq) accumulates 8 rows over a
//          32-k quarter; weight matrix crosses crossbar once per SM per step;
//          partials reduced with 2 butterfly shuffles (quad = adjacent lanes);
//          ONE barrier per step (double-buffered h).
// ---------------------------------------------------------------------------

typedef unsigned long long u64;

static __device__ __forceinline__ u64 pack2(float lo, float hi) {
    u64 r; asm("mov.b64 %0, {%1, %2};" : "=l"(r) : "f"(lo), "f"(hi)); return r;
}
static __device__ __forceinline__ void unpack2(u64 v, float& lo, float& hi) {
    asm("mov.b64 {%0, %1}, %2;" : "=f"(lo), "=f"(hi) : "l"(v));
}
static __device__ __forceinline__ u64 ffma2(u64 a, u64 b, u64 c) {
    u64 d; asm("fma.rn.f32x2 %0, %1, %2, %3;" : "=l"(d) : "l"(a), "l"(b), "l"(c)); return d;
}
static __device__ __forceinline__ void lds_v2u64(u64& a, u64& b, uint32_t addr) {
    asm volatile("ld.shared.v2.u64 {%0, %1}, [%2];" : "=l"(a), "=l"(b) : "r"(addr));
}
static __device__ __forceinline__ uint32_t smem_u32(const void* p) {
    uint32_t a;
    asm("{ .reg .u64 t; cvta.to.shared.u64 t, %1; cvt.u32.u64 %0, t; }" : "=r"(a) : "l"(p));
    return a;
}
static __device__ __forceinline__ void cp16(uint32_t dst, const void* src) {
    asm volatile("cp.async.cg.shared.global [%0], [%1], 16;" :: "r"(dst), "l"(src));
}
static __device__ __forceinline__ void cp_commit() { asm volatile("cp.async.commit_group;"); }
static __device__ __forceinline__ void cp_wait1()  { asm volatile("cp.async.wait_group 1;"); }
static __device__ __forceinline__ void cp_wait0()  { asm volatile("cp.async.wait_group 0;"); }
static __device__ __forceinline__ float sigf(float x) {
    return __fdividef(1.0f, 1.0f + __expf(-x));
}
static __device__ __forceinline__ float tanhf_fast(float x) {
    float ax = fabsf(x);
    float e  = __expf(-2.0f * ax);
    float t  = __fdividef(1.0f - e, 1.0f + e);
    return copysignf(t, x);
}

constexpr int H  = 128;
constexpr int G  = 384;    // 3*H
constexpr int TT = 512;
constexpr int BB = 1024;

// precomputed input gates: [T*B][3H]  (~805 MB static device scratch)
__device__ float g_xg[(size_t)TT * BB * G];

// shared weight tile: ws4[kk][g] (kk = k/4), 32*384*16 B
constexpr int WS_BYTES = 32 * G * 16;      // 196608
constexpr int RP       = 528;              // x row pitch in BYTES (132 floats)

// ---------------------------------------------------------------------------
// Phase 1: g_xg = input @ w_ih^T + b_ih   (persistent GEMM, cp.async staging)
// 512 threads; warp = u-octet; lane = rl*8+ul; thread: rows rl+4j (j=0..7).
// ---------------------------------------------------------------------------
constexpr int ROWS1    = 32;
constexpr int THR1     = 512;
constexpr int NBLK1    = (TT * BB) / ROWS1;   // 16384 tiles
constexpr int GRID1    = 148;
constexpr int XS_BYTES = ROWS1 * RP;          // 16896
constexpr int SMEM1    = WS_BYTES + 2 * XS_BYTES;   // 230400

__global__ void __launch_bounds__(THR1) xg_kernel(const float* __restrict__ input,
                                                  const float* __restrict__ w_ih,
                                                  const float* __restrict__ b_ih) {
    extern __shared__ char smem[];
    float4* ws4 = (float4*)smem;
    const uint32_t ws_a = smem_u32(smem);
    const uint32_t xs_a = ws_a + WS_BYTES;

    const int tid  = threadIdx.x;
    const int lane = tid & 31;
    const int wrp  = tid >> 5;
    const int ul   = lane & 7;
    const int rl   = lane >> 3;        // 0..3
    const int u    = wrp * 8 + ul;     // 0..127

    // stage tile 0 / tile 1 via cp.async while we also stage weights
    const int i0 = tid, i1 = tid + THR1;
    const uint32_t d0 = xs_a + (i0 >> 5) * RP + (i0 & 31) * 16;
    const uint32_t d1 = xs_a + (i1 >> 5) * RP + (i1 & 31) * 16;
    {
        const float4* in4 = (const float4*)(input + (size_t)blockIdx.x * ROWS1 * H);
        cp16(d0, in4 + i0); cp16(d1, in4 + i1); cp_commit();
        const float4* in4b = (const float4*)(input + (size_t)(blockIdx.x + GRID1) * ROWS1 * H);
        cp16(d0 + XS_BYTES, in4b + i0); cp16(d1 + XS_BYTES, in4b + i1); cp_commit();
    }

    // stage weights once: ws4[kk*384 + g] = w_ih[g][4kk..4kk+3]
    const float4* w4 = (const float4*)w_ih;
    for (int i = tid; i < G * 32; i += THR1) {
        int g = i >> 5, kk = i & 31;
        ws4[kk * G + g] = w4[g * 32 + kk];
    }
    const float br = b_ih[u], bz = b_ih[u + 128], bn = b_ih[u + 256];

    const uint32_t wb = ws_a + u * 16;
    int p = 0;

    for (int j = blockIdx.x; j < NBLK1; j += GRID1) {
        cp_wait1();          // buffer p filled
        __syncthreads();     // visible to all (also covers weight staging, 1st iter)

        const uint32_t xb = xs_a + p * XS_BYTES + rl * RP;   // + jj*4*RP + kk*16

        u64 aR[8], aZ[8], aN[8];
        #pragma unroll
        for (int r = 0; r < 8; r++) {
            aR[r] = pack2(br, 0.f); aZ[r] = pack2(bz, 0.f); aN[r] = pack2(bn, 0.f);
        }

        #pragma unroll 4
        for (int kk = 0; kk < 32; kk++) {
            u64 wr0, wr1, wz0, wz1, wn0, wn1;
            const uint32_t wo = wb + kk * (G * 16);
            lds_v2u64(wr0, wr1, wo);                 // 8 u x 16B, bcast x4 -> 1 cyc
            lds_v2u64(wz0, wz1, wo + 128 * 16);
            lds_v2u64(wn0, wn1, wo + 256 * 16);
            #pragma unroll
            for (int jj = 0; jj < 8; jj++) {
                u64 x0, x1;
                lds_v2u64(x0, x1, xb + jj * (4 * RP) + kk * 16);  // 4 rows bcast -> 1 cyc
                aR[jj] = ffma2(x0, wr0, aR[jj]); aR[jj] = ffma2(x1, wr1, aR[jj]);
                aZ[jj] = ffma2(x0, wz0, aZ[jj]); aZ[jj] = ffma2(x1, wz1, aZ[jj]);
                aN[jj] = ffma2(x0, wn0, aN[jj]); aN[jj] = ffma2(x1, wn1, aN[jj]);
            }
        }

        float* outp = g_xg + ((size_t)j * ROWS1 + rl) * G + u;
        #pragma unroll
        for (int jj = 0; jj < 8; jj++) {
            float l, h2;
            size_t ro = (size_t)(4 * jj) * G;
            unpack2(aR[jj], l, h2); outp[ro]       = l + h2;
            unpack2(aZ[jj], l, h2); outp[ro + 128] = l + h2;
            unpack2(aN[jj], l, h2); outp[ro + 256] = l + h2;
        }

        __syncthreads();     // everyone done reading buffer p
        int jn = j + 2 * GRID1;
        if (jn < NBLK1) {    // refill buffer p
            const float4* in4 = (const float4*)(input + (size_t)jn * ROWS1 * H);
            cp16(xs_a + p * XS_BYTES + (i0 >> 5) * RP + (i0 & 31) * 16, in4 + i0);
            cp16(xs_a + p * XS_BYTES + (i1 >> 5) * RP + (i1 & 31) * 16, in4 + i1);
        }
        cp_commit();         // commit even if empty (keeps wait accounting)
        p ^= 1;
    }
    cp_wait0();
}

// ---------------------------------------------------------------------------
// Phase 2: split-K-4 recurrence. 128 CTAs x 512 threads.
// thread (u = tid>>2, kq = tid&3): partial hg over k in [32kq,32kq+32) for
// all 8 rows; butterfly-shuffle reduce within lane quads; finalizes rows
// 2kq, 2kq+1. h rows stored quarter-padded (272B stride) -> conflict-free.
// ---------------------------------------------------------------------------
constexpr int THR2  = 512;
constexpr int HROW  = 1088;                 // bytes per h row: 4 quarters x 272
constexpr int HB    = 8 * HROW;             // 8704 per buffer
constexpr int SMEM2 = WS_BYTES + 2 * HB + 8 * H * 4;   // 218112

__global__ void __launch_bounds__(THR2) gru_kernel(const float* __restrict__ initial_h,
                                                   const float* __restrict__ w_hh,
                                                   const float* __restrict__ b_hh,
                                                   const float* __restrict__ w_out,
                                                   const float* __restrict__ b_out,
                                                   float* __restrict__ out) {
    extern __shared__ char smem[];
    float4* ws4 = (float4*)smem;
    float*  red = (float*)(smem + WS_BYTES + 2 * HB);   // [8][128]
    const uint32_t ws_a = smem_u32(smem);
    const uint32_t hs_a = ws_a + WS_BYTES;

    const int tid = threadIdx.x;
    const int kq  = tid & 3;           // k-quarter, also row-pair owner
    const int u   = tid >> 2;          // 0..127
    const int r0  = 2 * kq;            // own rows r0, r0+1
    const int b0  = blockIdx.x * 8;

    const float4* w4 = (const float4*)w_hh;
    for (int i = tid; i < G * 32; i += THR2) {
        int g = i >> 5, kk = i & 31;
        ws4[kk * G + g] = w4[g * 32 + kk];
    }
    const float br = b_hh[u], bz = b_hh[u + 128], bn = b_hh[u + 256];

    // h element address within a buffer: row*HROW + (u>>5)*272 + (u&31)*4
    const int hoff = (u >> 5) * 272 + (u & 31) * 4;

    // init h: thread writes its 2 rows (all 8 covered across kq)
    float hreg[2];
    #pragma unroll
    for (int i = 0; i < 2; i++) {
        int row = r0 + i;
        float v = initial_h[(size_t)(b0 + row) * H + u];
        hreg[i] = v;
        *(float*)(smem + WS_BYTES + row * HROW + hoff) = v;
    }

    // prefetch xg for t = 0 (own rows only)
    float cxR[2], cxZ[2], cxN[2];
    {
        const float* xg0 = g_xg + ((size_t)b0 + r0) * G + u;
        #pragma unroll
        for (int i = 0; i < 2; i++) {
            cxR[i] = xg0[(size_t)i * G];
            cxZ[i] = xg0[(size_t)i * G + 128];
            cxN[i] = xg0[(size_t)i * G + 256];
        }
    }
    __syncthreads();

    const uint32_t wb = ws_a + u * 16;      // + (8*kq + j)*(G*16)
    int p = 0;

    for (int t = 0; t < TT; t++) {
        // prefetch next step's xg (own rows)
        float nxR[2], nxZ[2], nxN[2];
        {
            int tn = (t + 1 < TT) ? (t + 1) : t;
            const float* xgn = g_xg + ((size_t)tn * BB + b0 + r0) * G + u;
            #pragma unroll
            for (int i = 0; i < 2; i++) {
                nxR[i] = xgn[(size_t)i * G];
                nxZ[i] = xgn[(size_t)i * G + 128];
                nxN[i] = xgn[(size_t)i * G + 256];
            }
        }

        u64 aR[8], aZ[8], aN[8];
        #pragma unroll
        for (int r = 0; r < 8; r++) { aR[r] = 0; aZ[r] = 0; aN[r] = 0; }

        const uint32_t hq = hs_a + p * HB + kq * 272;   // + row*HROW + jj*16

        #pragma unroll 4
        for (int jj = 0; jj < 8; jj++) {
            u64 wr0, wr1, wz0, wz1, wn0, wn1;
            const uint32_t wo = wb + (8 * kq + jj) * (G * 16);
            lds_v2u64(wr0, wr1, wo);                    // whole matrix once/SM/step
            lds_v2u64(wz0, wz1, wo + 128 * 16);
            lds_v2u64(wn0, wn1, wo + 256 * 16);
            #pragma unroll
            for (int row = 0; row < 8; row++) {
                u64 x0, x1;
                lds_v2u64(x0, x1, hq + row * HROW + jj * 16);   // 64B bcast -> 1 cyc
                aR[row] = ffma2(x0, wr0, aR[row]); aR[row] = ffma2(x1, wr1, aR[row]);
                aZ[row] = ffma2(x0, wz0, aZ[row]); aZ[row] = ffma2(x1, wz1, aZ[row]);
                aN[row] = ffma2(x0, wn0, aN[row]); aN[row] = ffma2(x1, wn1, aN[row]);
            }
        }

        // fold u64 -> float, butterfly-reduce across the lane quad (kq dim)
        float s[24];
        #pragma unroll
        for (int row = 0; row < 8; row++) {
            float l, h2;
            unpack2(aR[row], l, h2); s[row * 3 + 0] = l + h2;
            unpack2(aZ[row], l, h2); s[row * 3 + 1] = l + h2;
            unpack2(aN[row], l, h2); s[row * 3 + 2] = l + h2;
        }
        #pragma unroll
        for (int v = 0; v < 24; v++) {
            s[v] += __shfl_xor_sync(0xffffffffu, s[v], 1);
            s[v] += __shfl_xor_sync(0xffffffffu, s[v], 2);
        }

        // finalize own 2 rows; write h for next step into buffer p^1
        #pragma unroll
        for (int i = 0; i < 2; i++) {
            int row = r0 + i;
            float rg = sigf(cxR[i] + s[row * 3 + 0] + br);
            float zg = sigf(cxZ[i] + s[row * 3 + 1] + bz);
            float ng = tanhf_fast(cxN[i] + rg * (s[row * 3 + 2] + bn));
            hreg[i] = (1.0f - zg) * ng + zg * hreg[i];
            *(float*)(smem + WS_BYTES + (p ^ 1) * HB + row * HROW + hoff) = hreg[i];
            cxR[i] = nxR[i]; cxZ[i] = nxZ[i]; cxN[i] = nxN[i];
        }

        __syncthreads();   // single barrier per step
        p ^= 1;
    }

    // projection: out[b] = sum_u h[b][u]*w_out[u] + b_out (deterministic tree)
    const float wo = w_out[u];
    #pragma unroll
    for (int i = 0; i < 2; i++) red[(r0 + i) * H + u] = hreg[i] * wo;
    __syncthreads();
    for (int st = 64; st > 0; st >>= 1) {
        if (u < st) {
            #pragma unroll
            for (int i = 0; i < 2; i++)
                red[(r0 + i) * H + u] += red[(r0 + i) * H + u + st];
        }
        __syncthreads();
    }
    if (tid < 8) out[b0 + tid] = red[tid * H] + b_out[0];
}

// ---------------------------------------------------------------------------
// launch
// ---------------------------------------------------------------------------
extern "C" void kernel_launch(void* const* d_in, const int* in_sizes, int n_in,
                              void* d_out, int out_size) {
    const float* input     = (const float*)d_in[0];   // [T, B, H]
    const float* initial_h = (const float*)d_in[1];   // [B, H]
    const float* w_ih      = (const float*)d_in[2];   // [3H, H]
    const float* w_hh      = (const float*)d_in[3];   // [3H, H]
    const float* b_ih      = (const float*)d_in[4];   // [3H]
    const float* b_hh      = (const float*)d_in[5];   // [3H]
    const float* w_out     = (const float*)d_in[6];   // [1, H]
    const float* b_out     = (const float*)d_in[7];   // [1]
    float*       out       = (float*)d_out;           // [B, 1]

    (void)in_sizes; (void)n_in; (void)out_size;

    cudaFuncSetAttribute(xg_kernel,  cudaFuncAttributeMaxDynamicSharedMemorySize, SMEM1);
    cudaFuncSetAttribute(gru_kernel, cudaFuncAttributeMaxDynamicSharedMemorySize, SMEM2);

    xg_kernel<<<GRID1, THR1, SMEM1>>>(input, w_ih, b_ih);
    gru_kernel<<<BB / 8, THR2, SMEM2>>>(initial_h, w_hh, b_hh, w_out, b_out, out);
}

// round 13
// speedup vs baseline: 1.5343x; 1.5343x over previous
#include <cuda_runtime.h>
#include <math.h>
#include <stdint.h>

// ---------------------------------------------------------------------------
// GRU: T=512, B=1024, H=128.  out = h_T @ w_out^T + b_out
//
// Phase 1: persistent GEMM (unchanged from R12; crossbar-clean lane map).
// Phase 2: 512 threads, split-K-2 with lane map (ul, kh, s):
//   thread (u = wrp*8+ul, kh, s) accumulates rows s*4..s*4+3 over k-half kh.
//   - weight LDS: 8u x 2kh = 256B, two clean 128B phases (2 cyc); whole
//     w_hh crosses the crossbar exactly once per SM per step.
//   - h LDS: 4 distinct 16B, bank offsets {0,16,64,80} -> 1 cyc.
//   - reduce: ONE shfl_xor(8) per value; each thread finalizes 2 rows.
//   - ONE barrier per step (double-buffered h).
//   12 u64 accumulators -> ~80 regs, no spills at 512 thr.
// ---------------------------------------------------------------------------

typedef unsigned long long u64;

static __device__ __forceinline__ u64 pack2(float lo, float hi) {
    u64 r; asm("mov.b64 %0, {%1, %2};" : "=l"(r) : "f"(lo), "f"(hi)); return r;
}
static __device__ __forceinline__ void unpack2(u64 v, float& lo, float& hi) {
    asm("mov.b64 {%0, %1}, %2;" : "=f"(lo), "=f"(hi) : "l"(v));
}
static __device__ __forceinline__ u64 ffma2(u64 a, u64 b, u64 c) {
    u64 d; asm("fma.rn.f32x2 %0, %1, %2, %3;" : "=l"(d) : "l"(a), "l"(b), "l"(c)); return d;
}
static __device__ __forceinline__ void lds_v2u64(u64& a, u64& b, uint32_t addr) {
    asm volatile("ld.shared.v2.u64 {%0, %1}, [%2];" : "=l"(a), "=l"(b) : "r"(addr));
}
static __device__ __forceinline__ uint32_t smem_u32(const void* p) {
    uint32_t a;
    asm("{ .reg .u64 t; cvta.to.shared.u64 t, %1; cvt.u32.u64 %0, t; }" : "=r"(a) : "l"(p));
    return a;
}
static __device__ __forceinline__ void cp16(uint32_t dst, const void* src) {
    asm volatile("cp.async.cg.shared.global [%0], [%1], 16;" :: "r"(dst), "l"(src));
}
static __device__ __forceinline__ void cp_commit() { asm volatile("cp.async.commit_group;"); }
static __device__ __forceinline__ void cp_wait1()  { asm volatile("cp.async.wait_group 1;"); }
static __device__ __forceinline__ void cp_wait0()  { asm volatile("cp.async.wait_group 0;"); }
static __device__ __forceinline__ float sigf(float x) {
    return __fdividef(1.0f, 1.0f + __expf(-x));
}
static __device__ __forceinline__ float tanhf_fast(float x) {
    float ax = fabsf(x);
    float e  = __expf(-2.0f * ax);
    float t  = __fdividef(1.0f - e, 1.0f + e);
    return copysignf(t, x);
}

constexpr int H  = 128;
constexpr int G  = 384;    // 3*H
constexpr int TT = 512;
constexpr int BB = 1024;

// precomputed input gates: [T*B][3H]  (~805 MB static device scratch)
__device__ float g_xg[(size_t)TT * BB * G];

// shared weight tile: ws4[kk][g] (kk = k/4), 32*384*16 B
constexpr int WS_BYTES = 32 * G * 16;      // 196608
constexpr int RP       = 528;              // x row pitch in BYTES (132 floats)

// ---------------------------------------------------------------------------
// Phase 1: g_xg = input @ w_ih^T + b_ih   (persistent GEMM, cp.async staging)
// 512 threads; warp = u-octet; lane = rl*8+ul; thread: rows rl+4j (j=0..7).
// ---------------------------------------------------------------------------
constexpr int ROWS1    = 32;
constexpr int THR1     = 512;
constexpr int NBLK1    = (TT * BB) / ROWS1;   // 16384 tiles
constexpr int GRID1    = 148;
constexpr int XS_BYTES = ROWS1 * RP;          // 16896
constexpr int SMEM1    = WS_BYTES + 2 * XS_BYTES;   // 230400

__global__ void __launch_bounds__(THR1) xg_kernel(const float* __restrict__ input,
                                                  const float* __restrict__ w_ih,
                                                  const float* __restrict__ b_ih) {
    extern __shared__ char smem[];
    float4* ws4 = (float4*)smem;
    const uint32_t ws_a = smem_u32(smem);
    const uint32_t xs_a = ws_a + WS_BYTES;

    const int tid  = threadIdx.x;
    const int lane = tid & 31;
    const int wrp  = tid >> 5;
    const int ul   = lane & 7;
    const int rl   = lane >> 3;        // 0..3
    const int u    = wrp * 8 + ul;     // 0..127

    // stage tile 0 / tile 1 via cp.async while we also stage weights
    const int i0 = tid, i1 = tid + THR1;
    const uint32_t d0 = xs_a + (i0 >> 5) * RP + (i0 & 31) * 16;
    const uint32_t d1 = xs_a + (i1 >> 5) * RP + (i1 & 31) * 16;
    {
        const float4* in4 = (const float4*)(input + (size_t)blockIdx.x * ROWS1 * H);
        cp16(d0, in4 + i0); cp16(d1, in4 + i1); cp_commit();
        const float4* in4b = (const float4*)(input + (size_t)(blockIdx.x + GRID1) * ROWS1 * H);
        cp16(d0 + XS_BYTES, in4b + i0); cp16(d1 + XS_BYTES, in4b + i1); cp_commit();
    }

    // stage weights once: ws4[kk*384 + g] = w_ih[g][4kk..4kk+3]
    const float4* w4 = (const float4*)w_ih;
    for (int i = tid; i < G * 32; i += THR1) {
        int g = i >> 5, kk = i & 31;
        ws4[kk * G + g] = w4[g * 32 + kk];
    }
    const float br = b_ih[u], bz = b_ih[u + 128], bn = b_ih[u + 256];

    const uint32_t wb = ws_a + u * 16;
    int p = 0;

    for (int j = blockIdx.x; j < NBLK1; j += GRID1) {
        cp_wait1();          // buffer p filled
        __syncthreads();     // visible to all (also covers weight staging, 1st iter)

        const uint32_t xb = xs_a + p * XS_BYTES + rl * RP;   // + jj*4*RP + kk*16

        u64 aR[8], aZ[8], aN[8];
        #pragma unroll
        for (int r = 0; r < 8; r++) {
            aR[r] = pack2(br, 0.f); aZ[r] = pack2(bz, 0.f); aN[r] = pack2(bn, 0.f);
        }

        #pragma unroll 4
        for (int kk = 0; kk < 32; kk++) {
            u64 wr0, wr1, wz0, wz1, wn0, wn1;
            const uint32_t wo = wb + kk * (G * 16);
            lds_v2u64(wr0, wr1, wo);                 // 8 u x 16B, bcast x4 -> 1 cyc
            lds_v2u64(wz0, wz1, wo + 128 * 16);
            lds_v2u64(wn0, wn1, wo + 256 * 16);
            #pragma unroll
            for (int jj = 0; jj < 8; jj++) {
                u64 x0, x1;
                lds_v2u64(x0, x1, xb + jj * (4 * RP) + kk * 16);  // 4 rows bcast -> 1 cyc
                aR[jj] = ffma2(x0, wr0, aR[jj]); aR[jj] = ffma2(x1, wr1, aR[jj]);
                aZ[jj] = ffma2(x0, wz0, aZ[jj]); aZ[jj] = ffma2(x1, wz1, aZ[jj]);
                aN[jj] = ffma2(x0, wn0, aN[jj]); aN[jj] = ffma2(x1, wn1, aN[jj]);
            }
        }

        float* outp = g_xg + ((size_t)j * ROWS1 + rl) * G + u;
        #pragma unroll
        for (int jj = 0; jj < 8; jj++) {
            float l, h2;
            size_t ro = (size_t)(4 * jj) * G;
            unpack2(aR[jj], l, h2); outp[ro]       = l + h2;
            unpack2(aZ[jj], l, h2); outp[ro + 128] = l + h2;
            unpack2(aN[jj], l, h2); outp[ro + 256] = l + h2;
        }

        __syncthreads();     // everyone done reading buffer p
        int jn = j + 2 * GRID1;
        if (jn < NBLK1) {    // refill buffer p
            const float4* in4 = (const float4*)(input + (size_t)jn * ROWS1 * H);
            cp16(xs_a + p * XS_BYTES + (i0 >> 5) * RP + (i0 & 31) * 16, in4 + i0);
            cp16(xs_a + p * XS_BYTES + (i1 >> 5) * RP + (i1 & 31) * 16, in4 + i1);
        }
        cp_commit();         // commit even if empty (keeps wait accounting)
        p ^= 1;
    }
    cp_wait0();
}

// ---------------------------------------------------------------------------
// Phase 2: split-K-2 recurrence, 512 threads, 4 warps/SMSP.
// lane = ul | kh<<3 | s<<4;  u = wrp*8+ul.
// thread accumulates rows s*4..s*4+3 over k-half kh (12 u64 accs),
// reduces across kh with shfl_xor(8), finalizes rows s*4+kh*2+{0,1}.
// ---------------------------------------------------------------------------
constexpr int THR2   = 512;
constexpr int HPITCH = 560;                  // bytes per h row (pad: 4*HPITCH%128=64)
constexpr int HB     = 8 * HPITCH;           // 4480 per buffer
constexpr int SMEM2  = WS_BYTES + 2 * HB + 8 * H * 4;   // 209664

__global__ void __launch_bounds__(THR2) gru_kernel(const float* __restrict__ initial_h,
                                                   const float* __restrict__ w_hh,
                                                   const float* __restrict__ b_hh,
                                                   const float* __restrict__ w_out,
                                                   const float* __restrict__ b_out,
                                                   float* __restrict__ out) {
    extern __shared__ char smem[];
    float4* ws4 = (float4*)smem;
    float*  red = (float*)(smem + WS_BYTES + 2 * HB);   // [8][128]
    const uint32_t ws_a = smem_u32(smem);
    const uint32_t hs_a = ws_a + WS_BYTES;

    const int tid  = threadIdx.x;
    const int lane = tid & 31;
    const int wrp  = tid >> 5;
    const int ul   = lane & 7;
    const int kh   = (lane >> 3) & 1;   // k-half
    const int s    = lane >> 4;         // row quad
    const int u    = wrp * 8 + ul;      // 0..127
    const int r0   = s * 4 + kh * 2;    // own output rows: r0, r0+1
    const int b0   = blockIdx.x * 8;

    const float4* w4 = (const float4*)w_hh;
    for (int i = tid; i < G * 32; i += THR2) {
        int g = i >> 5, kk = i & 31;
        ws4[kk * G + g] = w4[g * 32 + kk];
    }
    const float br = b_hh[u], bz = b_hh[u + 128], bn = b_hh[u + 256];

    // h element offset within a row: k-half padded layout
    const int hcol = (u >> 6) * 272 + (u & 63) * 4;

    // init h: thread writes its 2 rows (all 8 covered across (kh,s))
    float hreg[2];
    #pragma unroll
    for (int i = 0; i < 2; i++) {
        int row = r0 + i;
        float v = initial_h[(size_t)(b0 + row) * H + u];
        hreg[i] = v;
        *(float*)(smem + WS_BYTES + row * HPITCH + hcol) = v;
    }

    // prefetch xg for t = 0 (own 2 rows)
    float cxR[2], cxZ[2], cxN[2];
    {
        const float* xg0 = g_xg + ((size_t)b0 + r0) * G + u;
        #pragma unroll
        for (int i = 0; i < 2; i++) {
            cxR[i] = xg0[(size_t)i * G];
            cxZ[i] = xg0[(size_t)i * G + 128];
            cxN[i] = xg0[(size_t)i * G + 256];
        }
    }
    __syncthreads();

    const uint32_t wb = ws_a + u * 16 + kh * 16 * (G * 16);
    int p = 0;

    for (int t = 0; t < TT; t++) {
        // prefetch next step's xg (own rows)
        float nxR[2], nxZ[2], nxN[2];
        {
            int tn = (t + 1 < TT) ? (t + 1) : t;
            const float* xgn = g_xg + ((size_t)tn * BB + b0 + r0) * G + u;
            #pragma unroll
            for (int i = 0; i < 2; i++) {
                nxR[i] = xgn[(size_t)i * G];
                nxZ[i] = xgn[(size_t)i * G + 128];
                nxN[i] = xgn[(size_t)i * G + 256];
            }
        }

        // accumulate rows s*4..s*4+3 over this thread's k-half
        u64 aR[4], aZ[4], aN[4];
        #pragma unroll
        for (int r = 0; r < 4; r++) { aR[r] = 0; aZ[r] = 0; aN[r] = 0; }

        const uint32_t hq = hs_a + p * HB + (s * 4) * HPITCH + kh * 272;

        #pragma unroll 4
        for (int jj = 0; jj < 16; jj++) {
            u64 wr0, wr1, wz0, wz1, wn0, wn1;
            const uint32_t wo = wb + jj * (G * 16);
            lds_v2u64(wr0, wr1, wo);                // 256B, 2 clean phases
            lds_v2u64(wz0, wz1, wo + 128 * 16);
            lds_v2u64(wn0, wn1, wo + 256 * 16);
            #pragma unroll
            for (int ri = 0; ri < 4; ri++) {
                u64 x0, x1;
                lds_v2u64(x0, x1, hq + ri * HPITCH + jj * 16);   // 64B bcast, 1 cyc
                aR[ri] = ffma2(x0, wr0, aR[ri]); aR[ri] = ffma2(x1, wr1, aR[ri]);
                aZ[ri] = ffma2(x0, wz0, aZ[ri]); aZ[ri] = ffma2(x1, wz1, aZ[ri]);
                aN[ri] = ffma2(x0, wn0, aN[ri]); aN[ri] = ffma2(x1, wn1, aN[ri]);
            }
        }

        // fold u64 -> float, reduce across kh (one butterfly)
        float sv[12];
        #pragma unroll
        for (int ri = 0; ri < 4; ri++) {
            float l, h2;
            unpack2(aR[ri], l, h2); sv[ri * 3 + 0] = l + h2;
            unpack2(aZ[ri], l, h2); sv[ri * 3 + 1] = l + h2;
            unpack2(aN[ri], l, h2); sv[ri * 3 + 2] = l + h2;
        }
        #pragma unroll
        for (int v = 0; v < 12; v++)
            sv[v] += __shfl_xor_sync(0xffffffffu, sv[v], 8);

        // finalize own 2 rows; write h for next step into buffer p^1
        #pragma unroll
        for (int i = 0; i < 2; i++) {
            int li = kh * 2 + i;                  // local row index in s-quad
            float rg = sigf(cxR[i] + sv[li * 3 + 0] + br);
            float zg = sigf(cxZ[i] + sv[li * 3 + 1] + bz);
            float ng = tanhf_fast(cxN[i] + rg * (sv[li * 3 + 2] + bn));
            hreg[i] = (1.0f - zg) * ng + zg * hreg[i];
            *(float*)(smem + WS_BYTES + (p ^ 1) * HB + (r0 + i) * HPITCH + hcol) = hreg[i];
            cxR[i] = nxR[i]; cxZ[i] = nxZ[i]; cxN[i] = nxN[i];
        }

        __syncthreads();   // single barrier per step
        p ^= 1;
    }

    // projection: out[b] = sum_u h[b][u]*w_out[u] + b_out (deterministic tree)
    const float wo = w_out[u];
    #pragma unroll
    for (int i = 0; i < 2; i++) red[(r0 + i) * H + u] = hreg[i] * wo;
    __syncthreads();
    for (int st = 64; st > 0; st >>= 1) {
        if (u < st) {
            #pragma unroll
            for (int i = 0; i < 2; i++)
                red[(r0 + i) * H + u] += red[(r0 + i) * H + u + st];
        }
        __syncthreads();
    }
    if (tid < 8) out[b0 + tid] = red[tid * H] + b_out[0];
}

// ---------------------------------------------------------------------------
// launch
// ---------------------------------------------------------------------------
extern "C" void kernel_launch(void* const* d_in, const int* in_sizes, int n_in,
                              void* d_out, int out_size) {
    const float* input     = (const float*)d_in[0];   // [T, B, H]
    const float* initial_h = (const float*)d_in[1];   // [B, H]
    const float* w_ih      = (const float*)d_in[2];   // [3H, H]
    const float* w_hh      = (const float*)d_in[3];   // [3H, H]
    const float* b_ih      = (const float*)d_in[4];   // [3H]
    const float* b_hh      = (const float*)d_in[5];   // [3H]
    const float* w_out     = (const float*)d_in[6];   // [1, H]
    const float* b_out     = (const float*)d_in[7];   // [1]
    float*       out       = (float*)d_out;           // [B, 1]

    (void)in_sizes; (void)n_in; (void)out_size;

    cudaFuncSetAttribute(xg_kernel,  cudaFuncAttributeMaxDynamicSharedMemorySize, SMEM1);
    cudaFuncSetAttribute(gru_kernel, cudaFuncAttributeMaxDynamicSharedMemorySize, SMEM2);

    xg_kernel<<<GRID1, THR1, SMEM1>>>(input, w_ih, b_ih);
    gru_kernel<<<BB / 8, THR2, SMEM2>>>(initial_h, w_hh, b_hh, w_out, b_out, out);
}